// round 9
// baseline (speedup 1.0000x reference)
#include <cuda_runtime.h>
#include <cuda_fp16.h>
#include <cuda_bf16.h>
#include <cstdint>

#define NN 4096
#define MM 2048
#define DD 1024
#define ITERS 100
#define SINK_BLOCKS 148
#define SINK_THREADS 1024

// ---------------- static scratch (no allocations allowed) ----------------
__device__ __nv_bfloat16 d_xhi[NN * DD];
__device__ __nv_bfloat16 d_xlo[NN * DD];
__device__ __nv_bfloat16 d_yhi[MM * DD];
__device__ __nv_bfloat16 d_ylo[MM * DD];
__device__ float d_xn[NN];
__device__ float d_yn[MM];
__device__ float d_C[NN * MM];        // cost matrix (fp32, 33.5MB)
__device__ __half d_Kh[NN * MM];      // Gibbs kernel (fp16 row-major)
__device__ __half d_KhT[MM * NN];     // Gibbs kernel transposed
__device__ float d_u[NN];
__device__ float d_v[MM];
__device__ int d_cmax_bits;
__device__ unsigned int d_bar_arrive;
__device__ unsigned int d_bar_release;
__device__ double d_dist;

// ---------------- helpers ----------------
__device__ __forceinline__ uint32_t smem_u32(const void* p) {
    uint32_t a;
    asm("{ .reg .u64 t; cvta.to.shared.u64 t, %1; cvt.u32.u64 %0, t; }" : "=r"(a) : "l"(p));
    return a;
}

#define LDSM4(r, addr) \
    asm volatile("ldmatrix.sync.aligned.m8n8.x4.shared.b16 {%0,%1,%2,%3}, [%4];" \
                 : "=r"((r)[0]), "=r"((r)[1]), "=r"((r)[2]), "=r"((r)[3]) : "r"(addr))

#define MMA16816(d, a, b0, b1) \
    asm volatile("mma.sync.aligned.m16n8k16.row.col.f32.bf16.bf16.f32 " \
                 "{%0,%1,%2,%3},{%4,%5,%6,%7},{%8,%9},{%0,%1,%2,%3};" \
                 : "+f"((d)[0]), "+f"((d)[1]), "+f"((d)[2]), "+f"((d)[3]) \
                 : "r"((a)[0]), "r"((a)[1]), "r"((a)[2]), "r"((a)[3]), "r"(b0), "r"(b1))

// ---------------- init ----------------
__global__ void init_kernel() {
    int j = blockIdx.x * blockDim.x + threadIdx.x;
    if (j < MM) d_v[j] = 1.0f / MM;
    if (j == 0) {
        d_cmax_bits = 0; d_bar_arrive = 0; d_bar_release = 0; d_dist = 0.0;
    }
}

// ---------------- row-min shift + squared norms + bf16 hi/lo split ----------------
__global__ __launch_bounds__(256) void prep_kernel(const float* __restrict__ x,
                                                   const float* __restrict__ y) {
    __shared__ float red[256];
    int b = blockIdx.x;
    const float* src;
    __nv_bfloat16 *hdst, *ldst;
    float* nrm;
    int row;
    if (b < NN) { row = b;      src = x + (size_t)row * DD; hdst = d_xhi + (size_t)row * DD; ldst = d_xlo + (size_t)row * DD; nrm = d_xn; }
    else        { row = b - NN; src = y + (size_t)row * DD; hdst = d_yhi + (size_t)row * DD; ldst = d_ylo + (size_t)row * DD; nrm = d_yn; }

    int tid = threadIdx.x;
    float vals[4];
    float vmin = 3.4e38f;
#pragma unroll
    for (int i = 0; i < 4; i++) {
        vals[i] = src[tid + i * 256];
        vmin = fminf(vmin, vals[i]);
    }
    red[tid] = vmin;
    __syncthreads();
    for (int s = 128; s > 0; s >>= 1) {
        if (tid < s) red[tid] = fminf(red[tid], red[tid + s]);
        __syncthreads();
    }
    vmin = red[0];
    __syncthreads();

    float ss = 0.0f;
#pragma unroll
    for (int i = 0; i < 4; i++) {
        float t = vals[i] - vmin;
        __nv_bfloat16 h = __float2bfloat16(t);
        float hf = __bfloat162float(h);
        hdst[tid + i * 256] = h;
        ldst[tid + i * 256] = __float2bfloat16(t - hf);
        ss += t * t;
    }
    red[tid] = ss;
    __syncthreads();
    for (int s = 128; s > 0; s >>= 1) {
        if (tid < s) red[tid] += red[tid + s];
        __syncthreads();
    }
    if (tid == 0) nrm[row] = red[0];
}

// ---------------- bf16-split GEMM via mma.sync (HMMA) + cost epilogue ----------------
#define KC 32
#define NCHUNK (DD / KC)            // 32
#define ROWSTR 80                   // bytes per smem row (32 bf16 data + 8 pad)
#define MAT_B (128 * ROWSTR)        // 10240
#define STAGE_B (4 * MAT_B)         // 40960
#define GEMM_SMEM (2 * STAGE_B)     // 81920

__global__ __launch_bounds__(256) void gemm_cost_kernel() {
    extern __shared__ char smem[];
    uint32_t sb = smem_u32(smem);

    int tid = threadIdx.x;
    int wid = tid >> 5, lane = tid & 31;
    int j0 = blockIdx.x * 128;  // y rows (output cols)
    int i0 = blockIdx.y * 128;  // x rows (output rows)

    int mat  = tid >> 6;        // 0:Ah 1:Al 2:Bh 3:Bl
    int w    = tid & 63;
    int colu = w & 3;
    int rb   = w >> 2;
    const __nv_bfloat16* gp = (mat == 0) ? d_xhi : (mat == 1) ? d_xlo
                            : (mat == 2) ? d_yhi : d_ylo;
    int rbase = (mat < 2) ? i0 : j0;
    const uint4* g4 = (const uint4*)gp + (size_t)rbase * (DD / 8);
    char* smat = smem + mat * MAT_B;

    int wm = wid >> 2, wn = wid & 3;
    int aoff[4], boff[2];
#pragma unroll
    for (int mt = 0; mt < 4; mt++)
        aoff[mt] = (wm * 64 + mt * 16 + (lane & 15)) * ROWSTR + (lane >> 4) * 16;
#pragma unroll
    for (int np = 0; np < 2; np++)
        boff[np] = (wn * 32 + np * 16 + (lane & 7) + ((lane >> 4) & 1) * 8) * ROWSTR
                 + ((lane >> 3) & 1) * 16;

    float acc[4][4][4];
#pragma unroll
    for (int mt = 0; mt < 4; mt++)
#pragma unroll
        for (int nt = 0; nt < 4; nt++)
#pragma unroll
            for (int r = 0; r < 4; r++) acc[mt][nt][r] = 0.0f;

    {
        uint4 v[8];
#pragma unroll
        for (int q = 0; q < 8; q++)
            v[q] = g4[(size_t)(rb + q * 16) * (DD / 8) + colu];
#pragma unroll
        for (int q = 0; q < 8; q++)
            *(uint4*)(smat + (rb + q * 16) * ROWSTR + colu * 16) = v[q];
    }
    __syncthreads();

    for (int kc = 0; kc < NCHUNK; kc++) {
        int p = kc & 1;
        uint4 v[8];
        if (kc + 1 < NCHUNK) {
#pragma unroll
            for (int q = 0; q < 8; q++)
                v[q] = g4[(size_t)(rb + q * 16) * (DD / 8) + (kc + 1) * 4 + colu];
        }

        uint32_t st = sb + p * STAGE_B;
#pragma unroll
        for (int ks = 0; ks < 2; ks++) {
            uint32_t ah[4][4], al[4][4], bh[2][4], bl[2][4];
#pragma unroll
            for (int mt = 0; mt < 4; mt++) {
                LDSM4(ah[mt], st + aoff[mt] + ks * 32);
                LDSM4(al[mt], st + MAT_B + aoff[mt] + ks * 32);
            }
#pragma unroll
            for (int np = 0; np < 2; np++) {
                LDSM4(bh[np], st + 2 * MAT_B + boff[np] + ks * 32);
                LDSM4(bl[np], st + 3 * MAT_B + boff[np] + ks * 32);
            }
#pragma unroll
            for (int mt = 0; mt < 4; mt++)
#pragma unroll
                for (int nt = 0; nt < 4; nt++) {
                    int np = nt >> 1, s = (nt & 1) * 2;
                    MMA16816(acc[mt][nt], ah[mt], bh[np][s], bh[np][s + 1]);
                    MMA16816(acc[mt][nt], ah[mt], bl[np][s], bl[np][s + 1]);
                    MMA16816(acc[mt][nt], al[mt], bh[np][s], bh[np][s + 1]);
                }
        }

        if (kc + 1 < NCHUNK) {
            char* sdst = smem + (p ^ 1) * STAGE_B + mat * MAT_B;
#pragma unroll
            for (int q = 0; q < 8; q++)
                *(uint4*)(sdst + (rb + q * 16) * ROWSTR + colu * 16) = v[q];
        }
        __syncthreads();
    }

    // ---- epilogue: C = max(xn + yn - 2G, 0) + global max ----
    float cmax = 0.0f;
    int mrow = lane >> 2;
    int ncol = (lane & 3) * 2;
#pragma unroll
    for (int mt = 0; mt < 4; mt++) {
        int i_a = i0 + wm * 64 + mt * 16 + mrow;
        int i_b = i_a + 8;
        float xa = d_xn[i_a], xb = d_xn[i_b];
#pragma unroll
        for (int nt = 0; nt < 4; nt++) {
            int j = j0 + wn * 32 + nt * 8 + ncol;
            float y0 = d_yn[j], y1 = d_yn[j + 1];
            float c0 = fmaxf(xa + y0 - 2.0f * acc[mt][nt][0], 0.0f);
            float c1 = fmaxf(xa + y1 - 2.0f * acc[mt][nt][1], 0.0f);
            float c2 = fmaxf(xb + y0 - 2.0f * acc[mt][nt][2], 0.0f);
            float c3 = fmaxf(xb + y1 - 2.0f * acc[mt][nt][3], 0.0f);
            *(float2*)(d_C + (size_t)i_a * MM + j) = make_float2(c0, c1);
            *(float2*)(d_C + (size_t)i_b * MM + j) = make_float2(c2, c3);
            cmax = fmaxf(cmax, fmaxf(fmaxf(c0, c1), fmaxf(c2, c3)));
        }
    }
#pragma unroll
    for (int o = 16; o > 0; o >>= 1)
        cmax = fmaxf(cmax, __shfl_xor_sync(0xffffffffu, cmax, o));
    if (lane == 0) atomicMax(&d_cmax_bits, __float_as_int(cmax));
}

// ---------------- Kh = fp16(exp(-10*C/cmax)), plus transposed copy KhT ----------------
__global__ __launch_bounds__(256) void expk_tr_kernel() {
    __shared__ __half t[64][72];
    float cmax = __int_as_float(d_cmax_bits);
    float s = -10.0f / cmax;
    int j0 = blockIdx.x * 64;
    int i0 = blockIdx.y * 64;
    int tx = threadIdx.x & 15;
    int ty = threadIdx.x >> 4;

#pragma unroll
    for (int p = 0; p < 4; p++) {
        int r = p * 16 + ty;
        int i = i0 + r;
        float4 c = *(const float4*)(d_C + (size_t)i * MM + j0 + tx * 4);
        __half h0 = __float2half_rn(expf(c.x * s));
        __half h1 = __float2half_rn(expf(c.y * s));
        __half h2 = __float2half_rn(expf(c.z * s));
        __half h3 = __float2half_rn(expf(c.w * s));
        __half2* dst = (__half2*)(d_Kh + (size_t)i * MM + j0 + tx * 4);
        dst[0] = __halves2half2(h0, h1);
        dst[1] = __halves2half2(h2, h3);
        t[r][tx * 4 + 0] = h0; t[r][tx * 4 + 1] = h1;
        t[r][tx * 4 + 2] = h2; t[r][tx * 4 + 3] = h3;
    }
    __syncthreads();
#pragma unroll
    for (int p = 0; p < 4; p++) {
        int jr = p * 16 + ty;
        int j = j0 + jr;
        __half2* dst = (__half2*)(d_KhT + (size_t)j * NN + i0 + tx * 4);
        dst[0] = __halves2half2(t[tx * 4 + 0][jr], t[tx * 4 + 1][jr]);
        dst[1] = __halves2half2(t[tx * 4 + 2][jr], t[tx * 4 + 3][jr]);
    }
}

// ---------------- persistent Sinkhorn ----------------
// Acq/rel grid barrier: no MEMBAR.GPU; arrive with atom.acq_rel, release via st.release.
__device__ __forceinline__ void grid_bar(unsigned int gen) {
    __syncthreads();
    if (threadIdx.x == 0) {
        unsigned int t;
        asm volatile("atom.acq_rel.gpu.global.add.u32 %0, [%1], %2;"
                     : "=r"(t) : "l"(&d_bar_arrive), "r"(1u) : "memory");
        if (t + 1u == gen * (unsigned int)gridDim.x) {
            asm volatile("st.release.gpu.global.u32 [%0], %1;"
                         :: "l"(&d_bar_release), "r"(gen) : "memory");
        } else {
            unsigned int cur;
            do {
                __nanosleep(32);
                asm volatile("ld.acquire.gpu.global.u32 %0, [%1];"
                             : "=r"(cur) : "l"(&d_bar_release) : "memory");
            } while ((int)(cur - gen) < 0);
        }
    }
    __syncthreads();
}

// Block bid owns Kh rows {bid + 148k, k<28} (112KB, L1-cached) and
// KhT cols {bid + 148k, k<14} (first 7 L1-cached = 56KB, rest __ldcg).
__global__ __launch_bounds__(SINK_THREADS, 1) void sinkhorn_kernel() {
    __shared__ float stage[NN];  // 16KB
    const float a  = 1.0f / NN;
    const float b  = 1.0f / MM;
    const float fi = (float)(0.5 / 0.6);

    int tid = threadIdx.x;
    int bid = blockIdx.x;
    int warp = tid >> 5, lane = tid & 31;
    unsigned int gen = 0;

    for (int it = 0; it < ITERS; ++it) {
        // stage v (512 float4)
        if (tid < MM / 4)
            ((float4*)stage)[tid] = __ldcg((const float4*)d_v + tid);
        __syncthreads();

        // Phase A: u = (a / Kh v)^fi ; 2 rows per warp, warps 0..13, L1-resident Kh
        if (warp < 14) {
            int k0 = warp * 2;
            int r0 = bid + 148 * k0;
            int r1 = bid + 148 * (k0 + 1);
            bool h1 = (r1 < NN);
            const uint4* K0 = (const uint4*)(d_Kh + (size_t)r0 * MM);
            const uint4* K1 = (const uint4*)(d_Kh + (size_t)(h1 ? r1 : r0) * MM);
            const float4* sv4 = (const float4*)stage;
            float acc0 = 0.0f, acc1 = 0.0f;
#pragma unroll
            for (int q = 0; q < 8; q++) {
                int idx = q * 32 + lane;
                uint4 ka = K0[idx];
                uint4 kb = K1[idx];
                float4 v0 = sv4[idx * 2];
                float4 v1 = sv4[idx * 2 + 1];
                float2 h;
                h = __half22float2(*(__half2*)&ka.x); acc0 = fmaf(h.x, v0.x, acc0); acc0 = fmaf(h.y, v0.y, acc0);
                h = __half22float2(*(__half2*)&ka.y); acc0 = fmaf(h.x, v0.z, acc0); acc0 = fmaf(h.y, v0.w, acc0);
                h = __half22float2(*(__half2*)&ka.z); acc0 = fmaf(h.x, v1.x, acc0); acc0 = fmaf(h.y, v1.y, acc0);
                h = __half22float2(*(__half2*)&ka.w); acc0 = fmaf(h.x, v1.z, acc0); acc0 = fmaf(h.y, v1.w, acc0);
                h = __half22float2(*(__half2*)&kb.x); acc1 = fmaf(h.x, v0.x, acc1); acc1 = fmaf(h.y, v0.y, acc1);
                h = __half22float2(*(__half2*)&kb.y); acc1 = fmaf(h.x, v0.z, acc1); acc1 = fmaf(h.y, v0.w, acc1);
                h = __half22float2(*(__half2*)&kb.z); acc1 = fmaf(h.x, v1.x, acc1); acc1 = fmaf(h.y, v1.y, acc1);
                h = __half22float2(*(__half2*)&kb.w); acc1 = fmaf(h.x, v1.z, acc1); acc1 = fmaf(h.y, v1.w, acc1);
            }
#pragma unroll
            for (int o = 16; o > 0; o >>= 1) {
                acc0 += __shfl_xor_sync(0xffffffffu, acc0, o);
                acc1 += __shfl_xor_sync(0xffffffffu, acc1, o);
            }
            if (lane == 0) {
                __stcg(&d_u[r0], powf(a / acc0, fi));
                if (h1) __stcg(&d_u[r1], powf(a / acc1, fi));
            }
        }
        gen++; grid_bar(gen);

        // stage u (1024 float4)
        ((float4*)stage)[tid] = __ldcg((const float4*)d_u + tid);
        __syncthreads();

        // Phase B: v = (b / KhT u)^fi ; 2 cols per warp, warps 0..6
        if (warp < 7) {
            int k0 = warp * 2;
            int c0 = bid + 148 * k0;
            int c1 = bid + 148 * (k0 + 1);
            bool h1 = (c1 < MM);
            bool l1a = (k0 < 7);
            bool l1b = (k0 + 1 < 7);
            const uint4* K0 = (const uint4*)(d_KhT + (size_t)c0 * NN);
            const uint4* K1 = (const uint4*)(d_KhT + (size_t)(h1 ? c1 : c0) * NN);
            const float4* su4 = (const float4*)stage;
            float acc0 = 0.0f, acc1 = 0.0f;
#pragma unroll 4
            for (int q = 0; q < 16; q++) {
                int idx = q * 32 + lane;
                uint4 ka = l1a ? K0[idx] : __ldcg(&K0[idx]);
                uint4 kb = l1b ? K1[idx] : __ldcg(&K1[idx]);
                float4 u0 = su4[idx * 2];
                float4 u1 = su4[idx * 2 + 1];
                float2 h;
                h = __half22float2(*(__half2*)&ka.x); acc0 = fmaf(h.x, u0.x, acc0); acc0 = fmaf(h.y, u0.y, acc0);
                h = __half22float2(*(__half2*)&ka.y); acc0 = fmaf(h.x, u0.z, acc0); acc0 = fmaf(h.y, u0.w, acc0);
                h = __half22float2(*(__half2*)&ka.z); acc0 = fmaf(h.x, u1.x, acc0); acc0 = fmaf(h.y, u1.y, acc0);
                h = __half22float2(*(__half2*)&ka.w); acc0 = fmaf(h.x, u1.z, acc0); acc0 = fmaf(h.y, u1.w, acc0);
                h = __half22float2(*(__half2*)&kb.x); acc1 = fmaf(h.x, u0.x, acc1); acc1 = fmaf(h.y, u0.y, acc1);
                h = __half22float2(*(__half2*)&kb.y); acc1 = fmaf(h.x, u0.z, acc1); acc1 = fmaf(h.y, u0.w, acc1);
                h = __half22float2(*(__half2*)&kb.z); acc1 = fmaf(h.x, u1.x, acc1); acc1 = fmaf(h.y, u1.y, acc1);
                h = __half22float2(*(__half2*)&kb.w); acc1 = fmaf(h.x, u1.z, acc1); acc1 = fmaf(h.y, u1.w, acc1);
            }
#pragma unroll
            for (int o = 16; o > 0; o >>= 1) {
                acc0 += __shfl_xor_sync(0xffffffffu, acc0, o);
                acc1 += __shfl_xor_sync(0xffffffffu, acc1, o);
            }
            if (lane == 0) {
                __stcg(&d_v[c0], powf(b / acc0, fi));
                if (h1) __stcg(&d_v[c1], powf(b / acc1, fi));
            }
        }
        gen++; grid_bar(gen);
    }
}

// ---------------- flow = u*K*v (K recomputed fp32), write transposed, dist ----------------
__global__ __launch_bounds__(1024) void flow_kernel(float* __restrict__ out) {
    __shared__ float tile[32][33];
    __shared__ float wsum[32];
    float cmax = __int_as_float(d_cmax_bits);
    float scale = -10.0f / cmax;
    int tx = threadIdx.x, ty = threadIdx.y;
    int j0 = blockIdx.x * 32;
    int i0 = blockIdx.y * 32;
    int i = i0 + ty, j = j0 + tx;
    size_t idx = (size_t)i * MM + j;

    float c = d_C[idx];
    float k = expf(c * scale);
    float f = d_u[i] * k * d_v[j];
    tile[ty][tx] = f;

    float contrib = c * f;
#pragma unroll
    for (int o = 16; o > 0; o >>= 1) contrib += __shfl_xor_sync(0xffffffffu, contrib, o);
    if (tx == 0) wsum[ty] = contrib;
    __syncthreads();
    if (ty == 0) {
        float s = wsum[tx];
#pragma unroll
        for (int o = 16; o > 0; o >>= 1) s += __shfl_xor_sync(0xffffffffu, s, o);
        if (tx == 0) atomicAdd(&d_dist, (double)s);
    }
    out[(size_t)(j0 + ty) * NN + (i0 + tx)] = tile[tx][ty];
}

__global__ void dist_kernel(float* __restrict__ out, int out_size) {
    int base = NN * MM;
    int j = base + blockIdx.x * blockDim.x + threadIdx.x;
    if (j < out_size) out[j] = (float)d_dist;
}

// ---------------- launch ----------------
extern "C" void kernel_launch(void* const* d_in, const int* in_sizes, int n_in,
                              void* d_out, int out_size) {
    const float* x = (const float*)d_in[0];
    const float* y = (const float*)d_in[1];
    if (n_in >= 2 && in_sizes[0] == MM * DD && in_sizes[1] == NN * DD) {
        const float* t = x; x = y; y = t;
    }
    float* out = (float*)d_out;

    cudaFuncSetAttribute(gemm_cost_kernel,
                         cudaFuncAttributeMaxDynamicSharedMemorySize, GEMM_SMEM);

    init_kernel<<<2, 1024>>>();
    prep_kernel<<<NN + MM, 256>>>(x, y);
    gemm_cost_kernel<<<dim3(MM / 128, NN / 128), 256, GEMM_SMEM>>>();
    expk_tr_kernel<<<dim3(MM / 64, NN / 64), 256>>>();
    sinkhorn_kernel<<<SINK_BLOCKS, SINK_THREADS>>>();
    flow_kernel<<<dim3(MM / 32, NN / 32), dim3(32, 32)>>>(out);

    int base = NN * MM;
    if (out_size > base) {
        int rem = out_size - base;
        dist_kernel<<<(rem + 255) / 256, 256>>>(out, out_size);
    }
}